// round 15
// baseline (speedup 1.0000x reference)
#include <cuda_runtime.h>

#define HQ    16
#define DD    128
#define KS    32
#define ST    16
#define BSZ   64
#define TOPN  16
#define WIN   512
#define NEGF  (-1e30f)
#define BIGF  (1e30f)
#define QSCALE 0.08838834764831845f   // 128^-0.5
#define TMAX  2048
#define MMAX  127

// ---------------- scratch (static device globals; no allocation) ----------------
__device__ __align__(16) float g_cmpk[MMAX * DD];
__device__ __align__(16) float g_cmpv[MMAX * DD];
__device__ int g_selblk[TMAX * TOPN];
__device__ int g_selcnt[TMAX];

__device__ __forceinline__ float sigmoidf_(float x) { return 1.f / (1.f + __expf(-x)); }

// ---------------- Kernel A: mean-pool compressed K/V ----------------
__global__ void compress_kernel(const float* __restrict__ k, const float* __restrict__ v) {
    int m = blockIdx.x, d = threadIdx.x;
    float ka = 0.f, va = 0.f;
    int base = m * ST;
#pragma unroll
    for (int i = 0; i < KS; i++) {
        ka += k[(base + i) * DD + d];
        va += v[(base + i) * DD + d];
    }
    g_cmpk[m * DD + d] = ka * (1.f / KS);
    g_cmpv[m * DD + d] = va * (1.f / KS);
}

// ---------------- Kernel B: compressed attention + slc_p + top-k ----------------
// CTA per t, 256 threads. Warp w owns heads {2w, 2w+1}.
// smem: sq[2048] | ckT[128*129] | sc[16*128] | sps[128] | l_s[16]
__global__ __launch_bounds__(256, 2) void cmp_attn_kernel(
    const float* __restrict__ q, const float* __restrict__ cw,
    float* __restrict__ out, int M) {
    int t = blockIdx.x, tid = threadIdx.x;
    int lane = tid & 31, w = tid >> 5;
    extern __shared__ float sm[];
    float* sq  = sm;            // 2048
    float* ckT = sm + 2048;     // 16512 (pitch 129, conflict-free)
    float* sc  = ckT + 16512;   // 2048
    float* sps = sc + 2048;     // 128
    float* l_s = sps + 128;     // 16

    // valid compressed tokens: m*ST + KS <= t+1
    int Mv = (t >= KS - 1) ? ((t - (KS - 1)) / ST + 1) : 0;

    for (int i = tid; i < HQ * DD; i += 256) sq[i] = q[t * HQ * DD + i] * QSCALE;
    for (int i = tid; i < M * DD; i += 256) {
        int m = i >> 7, d = i & 127;
        ckT[d * 129 + m] = g_cmpk[i];
    }
    __syncthreads();

    int h0 = 2 * w, h1 = h0 + 1;
    float l0 = 1.f, l1 = 1.f;
    if (Mv > 0) {
        float a0[4] = {0, 0, 0, 0}, a1[4] = {0, 0, 0, 0};
#pragma unroll 8
        for (int d = 0; d < DD; d++) {
            float q0 = sq[h0 * DD + d], q1 = sq[h1 * DD + d];
            const float* kp = &ckT[d * 129 + lane];
            float k0 = kp[0], k1 = kp[32], k2 = kp[64], k3 = kp[96];
            a0[0] += q0 * k0; a0[1] += q0 * k1; a0[2] += q0 * k2; a0[3] += q0 * k3;
            a1[0] += q1 * k0; a1[1] += q1 * k1; a1[2] += q1 * k2; a1[3] += q1 * k3;
        }
#pragma unroll
        for (int jj = 0; jj < 4; jj++) {
            int m = lane + 32 * jj;
            bool ok = (m < Mv);
            a0[jj] = ok ? a0[jj] : NEGF;
            a1[jj] = ok ? a1[jj] : NEGF;
        }
        float mx0 = fmaxf(fmaxf(a0[0], a0[1]), fmaxf(a0[2], a0[3]));
        float mx1 = fmaxf(fmaxf(a1[0], a1[1]), fmaxf(a1[2], a1[3]));
#pragma unroll
        for (int o = 16; o; o >>= 1) {
            mx0 = fmaxf(mx0, __shfl_xor_sync(~0u, mx0, o));
            mx1 = fmaxf(mx1, __shfl_xor_sync(~0u, mx1, o));
        }
        float s0 = 0.f, s1 = 0.f;
#pragma unroll
        for (int jj = 0; jj < 4; jj++) {
            a0[jj] = __expf(a0[jj] - mx0);
            a1[jj] = __expf(a1[jj] - mx1);
            s0 += a0[jj]; s1 += a1[jj];
        }
#pragma unroll
        for (int o = 16; o; o >>= 1) {
            s0 += __shfl_xor_sync(~0u, s0, o);
            s1 += __shfl_xor_sync(~0u, s1, o);
        }
        l0 = s0; l1 = s1;
#pragma unroll
        for (int jj = 0; jj < 4; jj++) {
            int m = lane + 32 * jj;
            sc[h0 * DD + m] = a0[jj];
            sc[h1 * DD + m] = a1[jj];
        }
        if (lane == 0) { l_s[h0] = s0; l_s[h1] = s1; }
    }
    __syncthreads();

    // ps[m] = sum_h p[h][m]
    if (tid < M) {
        float s = 0.f;
        if (Mv > 0) {
#pragma unroll
            for (int h = 0; h < HQ; h++) s += sc[h * DD + tid] / l_s[h];
        }
        sps[tid] = s;
    }
    __syncthreads();

    // PV: warp w -> heads h0,h1; lane owns 4 consecutive dims
    int d0 = lane * 4;
    float4 acc0 = make_float4(0.f, 0.f, 0.f, 0.f);
    float4 acc1 = make_float4(0.f, 0.f, 0.f, 0.f);
    if (Mv > 0) {
        for (int m = 0; m < Mv; m++) {
            float4 vv = *(const float4*)&g_cmpv[m * DD + d0];
            float p0 = sc[h0 * DD + m], p1 = sc[h1 * DD + m];
            acc0.x += p0 * vv.x; acc0.y += p0 * vv.y; acc0.z += p0 * vv.z; acc0.w += p0 * vv.w;
            acc1.x += p1 * vv.x; acc1.y += p1 * vv.y; acc1.z += p1 * vv.z; acc1.w += p1 * vv.w;
        }
        float i0 = 1.f / l0, i1 = 1.f / l1;
        acc0.x *= i0; acc0.y *= i0; acc0.z *= i0; acc0.w *= i0;
        acc1.x *= i1; acc1.y *= i1; acc1.z *= i1; acc1.w *= i1;
    }
    float wa = sigmoidf_(cw[t * HQ * 3 + h0 * 3 + 0]);
    float wb = sigmoidf_(cw[t * HQ * 3 + h1 * 3 + 0]);
    float4 o0 = make_float4(wa * acc0.x, wa * acc0.y, wa * acc0.z, wa * acc0.w);
    float4 o1 = make_float4(wb * acc1.x, wb * acc1.y, wb * acc1.z, wb * acc1.w);
    *(float4*)&out[t * HQ * DD + h0 * DD + d0] = o0;
    *(float4*)&out[t * HQ * DD + h1 * DD + d0] = o1;

    // top-k (matches jax.lax.top_k tie-breaking: descending value, lowest index first)
    if (tid == 0) {
        int cur = t >> 6;
        int NBv = ((int)gridDim.x + BSZ - 1) / BSZ;   // T/64
        float sp[32];
        for (int b = 0; b < NBv; b++) sp[b] = 0.f;
        for (int m = 0; m < Mv; m++) {
            float pm = sps[m];
            int b0 = m >> 2;
            if ((m & 3) == 3) { sp[b0] += 0.5f * pm; sp[b0 + 1] += 0.5f * pm; }
            else sp[b0] += pm;
        }
        for (int b = 0; b < NBv; b++) {
            if (b < 2 || b == cur) sp[b] = BIGF;       // forced (applied after future in ref)
            else if (b > cur) sp[b] = NEGF;            // future
        }
        int cnt = 0;
        for (int s = 0; s < TOPN; s++) {
            int bi = 0; float bv = sp[0];
            for (int b = 1; b < NBv; b++) if (sp[b] > bv) { bv = sp[b]; bi = b; }
            sp[bi] = -3.0e38f;
            if (bi <= cur) g_selblk[t * TOPN + cnt++] = bi;  // keep only causal-relevant blocks
        }
        g_selcnt[t] = cnt;
    }
}

// ---------------- Kernel C/D: block-sparse attention (mode 0: selected, mode 1: SWA) ----------------
// CTA per t, 256 threads. Warp w owns heads {2w,2w+1}; online-softmax state in uniform registers.
// smem: sq[2048] | skT[128*65] | sv[64*128] | sc[16*64]
__global__ __launch_bounds__(256, 2) void sel_swa_kernel(
    const float* __restrict__ q, const float* __restrict__ k,
    const float* __restrict__ v, const float* __restrict__ cw,
    float* __restrict__ out, int mode) {
    int t = blockIdx.x, tid = threadIdx.x;
    int lane = tid & 31, w = tid >> 5;
    extern __shared__ float sm[];
    float* sq  = sm;           // 2048
    float* skT = sm + 2048;    // 8320 (pitch 65)
    float* sv  = skT + 8320;   // 8192
    float* sc  = sv + 8192;    // 1024

    for (int i = tid; i < HQ * DD; i += 256) sq[i] = q[t * HQ * DD + i] * QSCALE;

    int lo = 0, bstart = 0, nt;
    if (mode == 0) {
        nt = g_selcnt[t];
    } else {
        lo = t - WIN + 1; if (lo < 0) lo = 0;
        bstart = lo >> 6;
        nt = (t >> 6) - bstart + 1;
    }

    int h0 = 2 * w, h1 = h0 + 1, d0 = lane * 4;
    float mr0 = NEGF, mr1 = NEGF, lr0 = 0.f, lr1 = 0.f;
    float A0[4] = {0, 0, 0, 0}, A1[4] = {0, 0, 0, 0};

    for (int it = 0; it < nt; it++) {
        int blk = (mode == 0) ? g_selblk[t * TOPN + it] : (bstart + it);
        int base = blk * BSZ;
        __syncthreads();  // previous tile fully consumed (also orders sq fill on it=0)
        // fill transposed K (conflict-free stride-65 writes), row-major V (float4)
        for (int i = tid; i < BSZ * DD; i += 256) {
            int j = i >> 7, d = i & 127;
            skT[d * 65 + j] = k[(base + j) * DD + d];
        }
        {
            const float4* gv4 = (const float4*)(v + (size_t)base * DD);
            float4* sv4 = (float4*)sv;
            for (int i = tid; i < BSZ * 32; i += 256) sv4[i] = gv4[i];
        }
        __syncthreads();

        // ---- scores: 2 heads x 2 keys per thread ----
        float s00 = 0.f, s01 = 0.f, s10 = 0.f, s11 = 0.f;
#pragma unroll 8
        for (int d = 0; d < DD; d++) {
            const float* kp = &skT[d * 65 + lane];
            float k0 = kp[0], k1 = kp[32];
            float q0 = sq[h0 * DD + d], q1 = sq[h1 * DD + d];
            s00 += q0 * k0; s01 += q0 * k1;
            s10 += q1 * k0; s11 += q1 * k1;
        }
        int tok0 = base + lane, tok1 = tok0 + 32;
        bool ok0 = (tok0 <= t) && (tok0 >= lo);
        bool ok1 = (tok1 <= t) && (tok1 >= lo);
        if (!ok0) { s00 = NEGF; s10 = NEGF; }
        if (!ok1) { s01 = NEGF; s11 = NEGF; }

        // ---- warp-local online softmax (uniform register state) ----
        float mx0 = fmaxf(s00, s01), mx1 = fmaxf(s10, s11);
#pragma unroll
        for (int o = 16; o; o >>= 1) {
            mx0 = fmaxf(mx0, __shfl_xor_sync(~0u, mx0, o));
            mx1 = fmaxf(mx1, __shfl_xor_sync(~0u, mx1, o));
        }
        float mn0 = fmaxf(mr0, mx0), mn1 = fmaxf(mr1, mx1);
        float f0 = __expf(mr0 - mn0), f1 = __expf(mr1 - mn1);
        mr0 = mn0; mr1 = mn1;
        float e00 = __expf(s00 - mn0), e01 = __expf(s01 - mn0);
        float e10 = __expf(s10 - mn1), e11 = __expf(s11 - mn1);
        float sum0 = e00 + e01, sum1 = e10 + e11;
#pragma unroll
        for (int o = 16; o; o >>= 1) {
            sum0 += __shfl_xor_sync(~0u, sum0, o);
            sum1 += __shfl_xor_sync(~0u, sum1, o);
        }
        lr0 = lr0 * f0 + sum0;
        lr1 = lr1 * f1 + sum1;
        sc[h0 * BSZ + lane] = e00; sc[h0 * BSZ + lane + 32] = e01;
        sc[h1 * BSZ + lane] = e10; sc[h1 * BSZ + lane + 32] = e11;
        __syncwarp();

        // ---- PV: rescale + accumulate ----
#pragma unroll
        for (int i = 0; i < 4; i++) { A0[i] *= f0; A1[i] *= f1; }
#pragma unroll 4
        for (int j = 0; j < BSZ; j++) {
            float4 vv = *(const float4*)&sv[j * DD + d0];
            float p0 = sc[h0 * BSZ + j], p1 = sc[h1 * BSZ + j];
            A0[0] += p0 * vv.x; A0[1] += p0 * vv.y; A0[2] += p0 * vv.z; A0[3] += p0 * vv.w;
            A1[0] += p1 * vv.x; A1[1] += p1 * vv.y; A1[2] += p1 * vv.z; A1[3] += p1 * vv.w;
        }
    }

    float i0 = 1.f / lr0, i1 = 1.f / lr1;
    int widx = (mode == 0) ? 1 : 2;
    float wa = sigmoidf_(cw[t * HQ * 3 + h0 * 3 + widx]);
    float wb = sigmoidf_(cw[t * HQ * 3 + h1 * 3 + widx]);
    float4* p0 = (float4*)&out[t * HQ * DD + h0 * DD + d0];
    float4 o0 = *p0;
    o0.x += wa * A0[0] * i0; o0.y += wa * A0[1] * i0;
    o0.z += wa * A0[2] * i0; o0.w += wa * A0[3] * i0;
    *p0 = o0;
    float4* p1 = (float4*)&out[t * HQ * DD + h1 * DD + d0];
    float4 o1 = *p1;
    o1.x += wb * A1[0] * i1; o1.y += wb * A1[1] * i1;
    o1.z += wb * A1[2] * i1; o1.w += wb * A1[3] * i1;
    *p1 = o1;
}

// ---------------- launch ----------------
extern "C" void kernel_launch(void* const* d_in, const int* in_sizes, int n_in,
                              void* d_out, int out_size) {
    const float* q  = (const float*)d_in[0];
    const float* k  = (const float*)d_in[1];
    const float* v  = (const float*)d_in[2];
    const float* cw = (const float*)d_in[3];
    float* out = (float*)d_out;

    int T = in_sizes[1] / DD;           // k is [T, 1, 128]
    int M = (T - KS) / ST + 1;          // compressed tokens

    size_t smB = (size_t)(2048 + 16512 + 2048 + 128 + 16) * sizeof(float);  // 83008
    size_t smC = (size_t)(2048 + 8320 + 8192 + 1024) * sizeof(float);       // 78336
    cudaFuncSetAttribute(cmp_attn_kernel, cudaFuncAttributeMaxDynamicSharedMemorySize, (int)smB);
    cudaFuncSetAttribute(sel_swa_kernel, cudaFuncAttributeMaxDynamicSharedMemorySize, (int)smC);

    compress_kernel<<<M, 128>>>(k, v);
    cmp_attn_kernel<<<T, 256, smB>>>(q, cw, out, M);
    sel_swa_kernel<<<T, 256, smC>>>(q, k, v, cw, out, 0);  // selected-block attention
    sel_swa_kernel<<<T, 256, smC>>>(q, k, v, cw, out, 1);  // sliding-window attention
}

// round 16
// speedup vs baseline: 1.0000x; 1.0000x over previous
#include <cuda_runtime.h>

#define HQ    16
#define DD    128
#define KS    32
#define ST    16
#define BSZ   64
#define TOPN  16
#define WIN   512
#define NEGF  (-1e30f)
#define BIGF  (1e30f)
#define QSCALE 0.08838834764831845f   // 128^-0.5
#define TMAX  2048
#define MMAX  127

// ---------------- scratch (static device globals; no allocation) ----------------
__device__ __align__(16) float g_cmpk[MMAX * DD];
__device__ __align__(16) float g_cmpv[MMAX * DD];
__device__ int g_selblk[TMAX * TOPN];
__device__ int g_selcnt[TMAX];

__device__ __forceinline__ float sigmoidf_(float x) { return 1.f / (1.f + __expf(-x)); }

// ---------------- Kernel A: mean-pool compressed K/V ----------------
__global__ void compress_kernel(const float* __restrict__ k, const float* __restrict__ v) {
    int m = blockIdx.x, d = threadIdx.x;
    float ka = 0.f, va = 0.f;
    int base = m * ST;
#pragma unroll
    for (int i = 0; i < KS; i++) {
        ka += k[(base + i) * DD + d];
        va += v[(base + i) * DD + d];
    }
    g_cmpk[m * DD + d] = ka * (1.f / KS);
    g_cmpv[m * DD + d] = va * (1.f / KS);
}

// ---------------- Kernel B: compressed attention + slc_p + top-k ----------------
// CTA per t, 256 threads. Warp w owns heads {2w, 2w+1}.
// smem: sq[2048] | ckT[128*129] | sc[16*128] | sps[128] | l_s[16]
__global__ __launch_bounds__(256, 2) void cmp_attn_kernel(
    const float* __restrict__ q, const float* __restrict__ cw,
    float* __restrict__ out, int M) {
    int t = blockIdx.x, tid = threadIdx.x;
    int lane = tid & 31, w = tid >> 5;
    extern __shared__ float sm[];
    float* sq  = sm;            // 2048
    float* ckT = sm + 2048;     // 16512 (pitch 129, conflict-free)
    float* sc  = ckT + 16512;   // 2048
    float* sps = sc + 2048;     // 128
    float* l_s = sps + 128;     // 16

    // valid compressed tokens: m*ST + KS <= t+1
    int Mv = (t >= KS - 1) ? ((t - (KS - 1)) / ST + 1) : 0;

    for (int i = tid; i < HQ * DD; i += 256) sq[i] = q[t * HQ * DD + i] * QSCALE;
    for (int i = tid; i < M * DD; i += 256) {
        int m = i >> 7, d = i & 127;
        ckT[d * 129 + m] = g_cmpk[i];
    }
    __syncthreads();

    int h0 = 2 * w, h1 = h0 + 1;
    float l0 = 1.f, l1 = 1.f;
    if (Mv > 0) {
        float a0[4] = {0, 0, 0, 0}, a1[4] = {0, 0, 0, 0};
#pragma unroll 8
        for (int d = 0; d < DD; d++) {
            float q0 = sq[h0 * DD + d], q1 = sq[h1 * DD + d];
            const float* kp = &ckT[d * 129 + lane];
            float k0 = kp[0], k1 = kp[32], k2 = kp[64], k3 = kp[96];
            a0[0] += q0 * k0; a0[1] += q0 * k1; a0[2] += q0 * k2; a0[3] += q0 * k3;
            a1[0] += q1 * k0; a1[1] += q1 * k1; a1[2] += q1 * k2; a1[3] += q1 * k3;
        }
#pragma unroll
        for (int jj = 0; jj < 4; jj++) {
            int m = lane + 32 * jj;
            bool ok = (m < Mv);
            a0[jj] = ok ? a0[jj] : NEGF;
            a1[jj] = ok ? a1[jj] : NEGF;
        }
        float mx0 = fmaxf(fmaxf(a0[0], a0[1]), fmaxf(a0[2], a0[3]));
        float mx1 = fmaxf(fmaxf(a1[0], a1[1]), fmaxf(a1[2], a1[3]));
#pragma unroll
        for (int o = 16; o; o >>= 1) {
            mx0 = fmaxf(mx0, __shfl_xor_sync(~0u, mx0, o));
            mx1 = fmaxf(mx1, __shfl_xor_sync(~0u, mx1, o));
        }
        float s0 = 0.f, s1 = 0.f;
#pragma unroll
        for (int jj = 0; jj < 4; jj++) {
            a0[jj] = __expf(a0[jj] - mx0);
            a1[jj] = __expf(a1[jj] - mx1);
            s0 += a0[jj]; s1 += a1[jj];
        }
#pragma unroll
        for (int o = 16; o; o >>= 1) {
            s0 += __shfl_xor_sync(~0u, s0, o);
            s1 += __shfl_xor_sync(~0u, s1, o);
        }
        l0 = s0; l1 = s1;
#pragma unroll
        for (int jj = 0; jj < 4; jj++) {
            int m = lane + 32 * jj;
            sc[h0 * DD + m] = a0[jj];
            sc[h1 * DD + m] = a1[jj];
        }
        if (lane == 0) { l_s[h0] = s0; l_s[h1] = s1; }
    }
    __syncthreads();

    // ps[m] = sum_h p[h][m]
    if (tid < M) {
        float s = 0.f;
        if (Mv > 0) {
#pragma unroll
            for (int h = 0; h < HQ; h++) s += sc[h * DD + tid] / l_s[h];
        }
        sps[tid] = s;
    }
    __syncthreads();

    // PV: warp w -> heads h0,h1; lane owns 4 consecutive dims
    int d0 = lane * 4;
    float4 acc0 = make_float4(0.f, 0.f, 0.f, 0.f);
    float4 acc1 = make_float4(0.f, 0.f, 0.f, 0.f);
    if (Mv > 0) {
        for (int m = 0; m < Mv; m++) {
            float4 vv = *(const float4*)&g_cmpv[m * DD + d0];
            float p0 = sc[h0 * DD + m], p1 = sc[h1 * DD + m];
            acc0.x += p0 * vv.x; acc0.y += p0 * vv.y; acc0.z += p0 * vv.z; acc0.w += p0 * vv.w;
            acc1.x += p1 * vv.x; acc1.y += p1 * vv.y; acc1.z += p1 * vv.z; acc1.w += p1 * vv.w;
        }
        float i0 = 1.f / l0, i1 = 1.f / l1;
        acc0.x *= i0; acc0.y *= i0; acc0.z *= i0; acc0.w *= i0;
        acc1.x *= i1; acc1.y *= i1; acc1.z *= i1; acc1.w *= i1;
    }
    float wa = sigmoidf_(cw[t * HQ * 3 + h0 * 3 + 0]);
    float wb = sigmoidf_(cw[t * HQ * 3 + h1 * 3 + 0]);
    float4 o0 = make_float4(wa * acc0.x, wa * acc0.y, wa * acc0.z, wa * acc0.w);
    float4 o1 = make_float4(wb * acc1.x, wb * acc1.y, wb * acc1.z, wb * acc1.w);
    *(float4*)&out[t * HQ * DD + h0 * DD + d0] = o0;
    *(float4*)&out[t * HQ * DD + h1 * DD + d0] = o1;

    // top-k (matches jax.lax.top_k tie-breaking: descending value, lowest index first)
    if (tid == 0) {
        int cur = t >> 6;
        int NBv = ((int)gridDim.x + BSZ - 1) / BSZ;   // T/64
        float sp[32];
        for (int b = 0; b < NBv; b++) sp[b] = 0.f;
        for (int m = 0; m < Mv; m++) {
            float pm = sps[m];
            int b0 = m >> 2;
            if ((m & 3) == 3) { sp[b0] += 0.5f * pm; sp[b0 + 1] += 0.5f * pm; }
            else sp[b0] += pm;
        }
        for (int b = 0; b < NBv; b++) {
            if (b < 2 || b == cur) sp[b] = BIGF;       // forced (applied after future in ref)
            else if (b > cur) sp[b] = NEGF;            // future
        }
        int cnt = 0;
        for (int s = 0; s < TOPN; s++) {
            int bi = 0; float bv = sp[0];
            for (int b = 1; b < NBv; b++) if (sp[b] > bv) { bv = sp[b]; bi = b; }
            sp[bi] = -3.0e38f;
            if (bi <= cur) g_selblk[t * TOPN + cnt++] = bi;  // keep only causal-relevant blocks
        }
        g_selcnt[t] = cnt;
    }
}

// ---------------- Kernel C/D: block-sparse attention (mode 0: selected, mode 1: SWA) ----------------
// CTA per t, 256 threads. Warp w owns heads {2w,2w+1}; online-softmax state in uniform registers.
// smem: sq[2048] | skT[128*65] | sv[64*128] | sc[16*64]
__global__ __launch_bounds__(256, 2) void sel_swa_kernel(
    const float* __restrict__ q, const float* __restrict__ k,
    const float* __restrict__ v, const float* __restrict__ cw,
    float* __restrict__ out, int mode) {
    int t = blockIdx.x, tid = threadIdx.x;
    int lane = tid & 31, w = tid >> 5;
    extern __shared__ float sm[];
    float* sq  = sm;           // 2048
    float* skT = sm + 2048;    // 8320 (pitch 65)
    float* sv  = skT + 8320;   // 8192
    float* sc  = sv + 8192;    // 1024

    for (int i = tid; i < HQ * DD; i += 256) sq[i] = q[t * HQ * DD + i] * QSCALE;

    int lo = 0, bstart = 0, nt;
    if (mode == 0) {
        nt = g_selcnt[t];
    } else {
        lo = t - WIN + 1; if (lo < 0) lo = 0;
        bstart = lo >> 6;
        nt = (t >> 6) - bstart + 1;
    }

    int h0 = 2 * w, h1 = h0 + 1, d0 = lane * 4;
    float mr0 = NEGF, mr1 = NEGF, lr0 = 0.f, lr1 = 0.f;
    float A0[4] = {0, 0, 0, 0}, A1[4] = {0, 0, 0, 0};

    for (int it = 0; it < nt; it++) {
        int blk = (mode == 0) ? g_selblk[t * TOPN + it] : (bstart + it);
        int base = blk * BSZ;
        __syncthreads();  // previous tile fully consumed (also orders sq fill on it=0)
        // fill transposed K (conflict-free stride-65 writes), row-major V (float4)
        for (int i = tid; i < BSZ * DD; i += 256) {
            int j = i >> 7, d = i & 127;
            skT[d * 65 + j] = k[(base + j) * DD + d];
        }
        {
            const float4* gv4 = (const float4*)(v + (size_t)base * DD);
            float4* sv4 = (float4*)sv;
            for (int i = tid; i < BSZ * 32; i += 256) sv4[i] = gv4[i];
        }
        __syncthreads();

        // ---- scores: 2 heads x 2 keys per thread ----
        float s00 = 0.f, s01 = 0.f, s10 = 0.f, s11 = 0.f;
#pragma unroll 8
        for (int d = 0; d < DD; d++) {
            const float* kp = &skT[d * 65 + lane];
            float k0 = kp[0], k1 = kp[32];
            float q0 = sq[h0 * DD + d], q1 = sq[h1 * DD + d];
            s00 += q0 * k0; s01 += q0 * k1;
            s10 += q1 * k0; s11 += q1 * k1;
        }
        int tok0 = base + lane, tok1 = tok0 + 32;
        bool ok0 = (tok0 <= t) && (tok0 >= lo);
        bool ok1 = (tok1 <= t) && (tok1 >= lo);
        if (!ok0) { s00 = NEGF; s10 = NEGF; }
        if (!ok1) { s01 = NEGF; s11 = NEGF; }

        // ---- warp-local online softmax (uniform register state) ----
        float mx0 = fmaxf(s00, s01), mx1 = fmaxf(s10, s11);
#pragma unroll
        for (int o = 16; o; o >>= 1) {
            mx0 = fmaxf(mx0, __shfl_xor_sync(~0u, mx0, o));
            mx1 = fmaxf(mx1, __shfl_xor_sync(~0u, mx1, o));
        }
        float mn0 = fmaxf(mr0, mx0), mn1 = fmaxf(mr1, mx1);
        float f0 = __expf(mr0 - mn0), f1 = __expf(mr1 - mn1);
        mr0 = mn0; mr1 = mn1;
        float e00 = __expf(s00 - mn0), e01 = __expf(s01 - mn0);
        float e10 = __expf(s10 - mn1), e11 = __expf(s11 - mn1);
        float sum0 = e00 + e01, sum1 = e10 + e11;
#pragma unroll
        for (int o = 16; o; o >>= 1) {
            sum0 += __shfl_xor_sync(~0u, sum0, o);
            sum1 += __shfl_xor_sync(~0u, sum1, o);
        }
        lr0 = lr0 * f0 + sum0;
        lr1 = lr1 * f1 + sum1;
        sc[h0 * BSZ + lane] = e00; sc[h0 * BSZ + lane + 32] = e01;
        sc[h1 * BSZ + lane] = e10; sc[h1 * BSZ + lane + 32] = e11;
        __syncwarp();

        // ---- PV: rescale + accumulate ----
#pragma unroll
        for (int i = 0; i < 4; i++) { A0[i] *= f0; A1[i] *= f1; }
#pragma unroll 4
        for (int j = 0; j < BSZ; j++) {
            float4 vv = *(const float4*)&sv[j * DD + d0];
            float p0 = sc[h0 * BSZ + j], p1 = sc[h1 * BSZ + j];
            A0[0] += p0 * vv.x; A0[1] += p0 * vv.y; A0[2] += p0 * vv.z; A0[3] += p0 * vv.w;
            A1[0] += p1 * vv.x; A1[1] += p1 * vv.y; A1[2] += p1 * vv.z; A1[3] += p1 * vv.w;
        }
    }

    float i0 = 1.f / lr0, i1 = 1.f / lr1;
    int widx = (mode == 0) ? 1 : 2;
    float wa = sigmoidf_(cw[t * HQ * 3 + h0 * 3 + widx]);
    float wb = sigmoidf_(cw[t * HQ * 3 + h1 * 3 + widx]);
    float4* p0 = (float4*)&out[t * HQ * DD + h0 * DD + d0];
    float4 o0 = *p0;
    o0.x += wa * A0[0] * i0; o0.y += wa * A0[1] * i0;
    o0.z += wa * A0[2] * i0; o0.w += wa * A0[3] * i0;
    *p0 = o0;
    float4* p1 = (float4*)&out[t * HQ * DD + h1 * DD + d0];
    float4 o1 = *p1;
    o1.x += wb * A1[0] * i1; o1.y += wb * A1[1] * i1;
    o1.z += wb * A1[2] * i1; o1.w += wb * A1[3] * i1;
    *p1 = o1;
}

// ---------------- launch ----------------
extern "C" void kernel_launch(void* const* d_in, const int* in_sizes, int n_in,
                              void* d_out, int out_size) {
    const float* q  = (const float*)d_in[0];
    const float* k  = (const float*)d_in[1];
    const float* v  = (const float*)d_in[2];
    const float* cw = (const float*)d_in[3];
    float* out = (float*)d_out;

    int T = in_sizes[1] / DD;           // k is [T, 1, 128]
    int M = (T - KS) / ST + 1;          // compressed tokens

    size_t smB = (size_t)(2048 + 16512 + 2048 + 128 + 16) * sizeof(float);  // 83008
    size_t smC = (size_t)(2048 + 8320 + 8192 + 1024) * sizeof(float);       // 78336
    cudaFuncSetAttribute(cmp_attn_kernel, cudaFuncAttributeMaxDynamicSharedMemorySize, (int)smB);
    cudaFuncSetAttribute(sel_swa_kernel, cudaFuncAttributeMaxDynamicSharedMemorySize, (int)smC);

    compress_kernel<<<M, 128>>>(k, v);
    cmp_attn_kernel<<<T, 256, smB>>>(q, cw, out, M);
    sel_swa_kernel<<<T, 256, smC>>>(q, k, v, cw, out, 0);  // selected-block attention
    sel_swa_kernel<<<T, 256, smC>>>(q, k, v, cw, out, 1);  // sliding-window attention
}